// round 1
// baseline (speedup 1.0000x reference)
#include <cuda_runtime.h>

// ---------------------------------------------------------------------------
// PillarMaxPooling: h = relu((x @ W) * bn_scale + bn_shift); segment_max -> M pillars
// Strategy: counting-bucket inversion (no output atomics), then warp-per-pillar
// gather with packed f32x2 FMA mainloop. BN scale folded into W (max commutes
// with the affine applied pre-max), shift+relu applied once per pillar.
// ---------------------------------------------------------------------------

#define CAP      64
#define MAXM     262144
#define OVFCAP   65536
#define BN_EPS   1e-3f
#define K2_THREADS 256
#define K2_WARPS   8

__device__ int   d_count[MAXM];
__device__ int   d_bucket[(size_t)MAXM * CAP];
__device__ int   d_ovflist[OVFCAP];
__device__ int   d_ovfcnt;
__device__ float d_scale[64];
__device__ float d_shift[64];

typedef unsigned long long u64;

__device__ __forceinline__ u64 pk2(float x, float y) {
    u64 r; asm("mov.b64 %0, {%1, %2};" : "=l"(r) : "f"(x), "f"(y)); return r;
}
__device__ __forceinline__ void upk2(u64 v, float& x, float& y) {
    asm("mov.b64 {%0, %1}, %2;" : "=f"(x), "=f"(y) : "l"(v));
}
__device__ __forceinline__ u64 fma2(u64 a, u64 b, u64 c) {
    u64 d; asm("fma.rn.f32x2 %0, %1, %2, %3;" : "=l"(d) : "l"(a), "l"(b), "l"(c)); return d;
}
__device__ __forceinline__ u64 mul2(u64 a, u64 b) {
    u64 d; asm("mul.rn.f32x2 %0, %1, %2;" : "=l"(d) : "l"(a), "l"(b)); return d;
}
__device__ __forceinline__ u64 add2(u64 a, u64 b) {
    u64 d; asm("add.rn.f32x2 %0, %1, %2;" : "=l"(d) : "l"(a), "l"(b)); return d;
}

// K0: zero counters, fold BN into per-channel scale/shift.
__global__ void k0_init(const float* __restrict__ gamma, const float* __restrict__ beta,
                        const float* __restrict__ mean,  const float* __restrict__ var, int M) {
    int i = blockIdx.x * blockDim.x + threadIdx.x;
    if (i < M) d_count[i] = 0;
    if (i < 64) {
        float s = gamma[i] * rsqrtf(var[i] + BN_EPS);
        d_scale[i] = s;
        d_shift[i] = beta[i] - mean[i] * s;
    }
    if (i == 0) d_ovfcnt = 0;
}

// K1: bucket the point ids per pillar (counting-sort style, no scan needed).
__global__ void k1_scatter(const int* __restrict__ idx, int P) {
    int p = blockIdx.x * blockDim.x + threadIdx.x;
    if (p >= P) return;
    int i = idx[p];
    int s = atomicAdd(&d_count[i], 1);
    if (s < CAP) {
        d_bucket[(size_t)i * CAP + s] = p;
    } else {
        int o = atomicAdd(&d_ovfcnt, 1);
        if (o < OVFCAP) d_ovflist[o] = p;
    }
}

// K2: warp per pillar. Lane l owns channels (l, l+32) as one f32x2 pair.
// Points staged into SMEM as pre-splatted {f,f} pairs so the dot product is
// pure fma.rn.f32x2 against register-resident (scale-folded) W pairs.
__global__ void __launch_bounds__(K2_THREADS)
k2_compute(const float* __restrict__ gf, const float* __restrict__ W,
           float* __restrict__ out, int M) {
    __shared__ u64 sm[K2_WARPS][32][10];   // 32 points x 10 splatted pairs / warp

    int lane  = threadIdx.x & 31;
    int wloc  = threadIdx.x >> 5;
    u64* mysm = &sm[wloc][0][0];

    int gwarp = (blockIdx.x * K2_THREADS + threadIdx.x) >> 5;
    int nwarp = (gridDim.x * K2_THREADS) >> 5;

    float sx = d_scale[lane],      sy = d_scale[lane + 32];
    float bx = d_shift[lane],      by = d_shift[lane + 32];

    u64 w[10];
#pragma unroll
    for (int k = 0; k < 10; k++)
        w[k] = pk2(W[k * 64 + lane] * sx, W[k * 64 + lane + 32] * sy);

    for (int i = gwarp; i < M; i += nwarp) {
        int n = d_count[i];
        if (n > CAP) n = CAP;
        float mx = -3.402823e38f, my = -3.402823e38f;

        for (int base = 0; base < n; base += 32) {
            int m = n - base; if (m > 32) m = 32;
            __syncwarp();
            if (lane < m) {
                int pid = d_bucket[(size_t)i * CAP + base + lane];
                const float2* f = reinterpret_cast<const float2*>(gf + (size_t)pid * 10);
                float2 v0 = f[0], v1 = f[1], v2 = f[2], v3 = f[3], v4 = f[4];
                u64* r = mysm + lane * 10;
                r[0] = pk2(v0.x, v0.x); r[1] = pk2(v0.y, v0.y);
                r[2] = pk2(v1.x, v1.x); r[3] = pk2(v1.y, v1.y);
                r[4] = pk2(v2.x, v2.x); r[5] = pk2(v2.y, v2.y);
                r[6] = pk2(v3.x, v3.x); r[7] = pk2(v3.y, v3.y);
                r[8] = pk2(v4.x, v4.x); r[9] = pk2(v4.y, v4.y);
            }
            __syncwarp();
#pragma unroll 2
            for (int j = 0; j < m; j++) {
                const ulonglong2* q = reinterpret_cast<const ulonglong2*>(mysm + j * 10);
                ulonglong2 q0 = q[0], q1 = q[1], q2 = q[2], q3 = q[3], q4 = q[4];
                u64 a = mul2(q0.x, w[0]);
                u64 b = mul2(q0.y, w[1]);
                a = fma2(q1.x, w[2], a);  b = fma2(q1.y, w[3], b);
                a = fma2(q2.x, w[4], a);  b = fma2(q2.y, w[5], b);
                a = fma2(q3.x, w[6], a);  b = fma2(q3.y, w[7], b);
                a = fma2(q4.x, w[8], a);  b = fma2(q4.y, w[9], b);
                u64 s = add2(a, b);
                float dx, dy; upk2(s, dx, dy);
                mx = fmaxf(mx, dx);
                my = fmaxf(my, dy);
            }
        }

        float r0 = 0.0f, r1 = 0.0f;
        if (n > 0) {
            r0 = fmaxf(mx + bx, 0.0f);
            r1 = fmaxf(my + by, 0.0f);
        }
        out[(size_t)i * 64 + lane]      = r0;
        out[(size_t)i * 64 + lane + 32] = r1;
    }
}

// K3: overflow cleanup (expected zero work). atomicMax on fp32 bits is valid
// because all pooled values are >= 0 (relu outputs and a 0-initialized floor).
__global__ void k3_overflow(const float* __restrict__ gf, const int* __restrict__ idx,
                            const float* __restrict__ W, float* __restrict__ out) {
    int nov = d_ovfcnt;
    if (nov > OVFCAP) nov = OVFCAP;
    if (nov == 0) return;

    int lane  = threadIdx.x & 31;
    int gwarp = (blockIdx.x * blockDim.x + threadIdx.x) >> 5;
    int nwarp = (gridDim.x * blockDim.x) >> 5;

    float sx = d_scale[lane], sy = d_scale[lane + 32];
    float bx = d_shift[lane], by = d_shift[lane + 32];
    float wx[10], wy[10];
#pragma unroll
    for (int k = 0; k < 10; k++) {
        wx[k] = W[k * 64 + lane] * sx;
        wy[k] = W[k * 64 + lane + 32] * sy;
    }

    for (int t = gwarp; t < nov; t += nwarp) {
        int pid = d_ovflist[t];
        int pi  = idx[pid];
        float ax = 0.0f, ay = 0.0f;
#pragma unroll
        for (int k = 0; k < 10; k++) {
            float f = gf[(size_t)pid * 10 + k];
            ax = fmaf(f, wx[k], ax);
            ay = fmaf(f, wy[k], ay);
        }
        float r0 = fmaxf(ax + bx, 0.0f);
        float r1 = fmaxf(ay + by, 0.0f);
        atomicMax((int*)&out[(size_t)pi * 64 + lane],      __float_as_int(r0));
        atomicMax((int*)&out[(size_t)pi * 64 + lane + 32], __float_as_int(r1));
    }
}

extern "C" void kernel_launch(void* const* d_in, const int* in_sizes, int n_in,
                              void* d_out, int out_size) {
    const float* gf    = (const float*)d_in[0];
    const int*   idx   = (const int*)  d_in[1];
    const float* W     = (const float*)d_in[3];
    const float* gamma = (const float*)d_in[4];
    const float* beta  = (const float*)d_in[5];
    const float* mean  = (const float*)d_in[6];
    const float* var   = (const float*)d_in[7];
    float*       out   = (float*)d_out;

    int P = in_sizes[1];
    int M = out_size / 64;

    int t  = 256;
    int g0 = ((M > 64 ? M : 64) + t - 1) / t;
    int g1 = (P + t - 1) / t;

    k0_init<<<g0, t>>>(gamma, beta, mean, var, M);
    k1_scatter<<<g1, t>>>(idx, P);
    k2_compute<<<592, K2_THREADS>>>(gf, W, out, M);
    k3_overflow<<<8, 256>>>(gf, idx, W, out);
}

// round 2
// speedup vs baseline: 1.1331x; 1.1331x over previous
#include <cuda_runtime.h>

// ---------------------------------------------------------------------------
// PillarMaxPooling: h = relu((x @ W) * bn_scale + bn_shift); segment_max -> M
// Counting-bucket inversion (no output atomics) + warp-per-pillar gather.
// Mainloop: pair-packed f32x2 — each fma2 chain computes the dot of TWO points
// against one (scale-folded) weight column. Lane owns channels (l, l+32).
// ---------------------------------------------------------------------------

#define CAP      64
#define MAXM     262144
#define OVFCAP   65536
#define BN_EPS   1e-3f
#define K2_THREADS 256
#define K2_WARPS   8

__device__ int   d_count[MAXM];
__device__ int   d_bucket[(size_t)MAXM * CAP];
__device__ int   d_ovflist[OVFCAP];
__device__ int   d_ovfcnt;
__device__ float d_scale[64];
__device__ float d_shift[64];

typedef unsigned long long u64;

__device__ __forceinline__ u64 pk2(float x, float y) {
    u64 r; asm("mov.b64 %0, {%1, %2};" : "=l"(r) : "f"(x), "f"(y)); return r;
}
__device__ __forceinline__ void upk2(u64 v, float& x, float& y) {
    asm("mov.b64 {%0, %1}, %2;" : "=f"(x), "=f"(y) : "l"(v));
}
__device__ __forceinline__ u64 fma2(u64 a, u64 b, u64 c) {
    u64 d; asm("fma.rn.f32x2 %0, %1, %2, %3;" : "=l"(d) : "l"(a), "l"(b), "l"(c)); return d;
}
__device__ __forceinline__ u64 mul2(u64 a, u64 b) {
    u64 d; asm("mul.rn.f32x2 %0, %1, %2;" : "=l"(d) : "l"(a), "l"(b)); return d;
}

// K0: zero counters, fold BN into per-channel scale/shift.
__global__ void k0_init(const float* __restrict__ gamma, const float* __restrict__ beta,
                        const float* __restrict__ mean,  const float* __restrict__ var, int M) {
    int i = blockIdx.x * blockDim.x + threadIdx.x;
    if (i < M) d_count[i] = 0;
    if (i < 64) {
        float s = gamma[i] * rsqrtf(var[i] + BN_EPS);
        d_scale[i] = s;
        d_shift[i] = beta[i] - mean[i] * s;
    }
    if (i == 0) d_ovfcnt = 0;
}

// K1: bucket the point ids per pillar. int2-vectorized index read.
__global__ void k1_scatter(const int* __restrict__ idx, int P) {
    int t = blockIdx.x * blockDim.x + threadIdx.x;
    int p0 = t * 2;
    if (p0 + 1 < P) {
        int2 v = *reinterpret_cast<const int2*>(idx + p0);
#pragma unroll
        for (int u = 0; u < 2; u++) {
            int i = (u == 0) ? v.x : v.y;
            int s = atomicAdd(&d_count[i], 1);
            if (s < CAP) d_bucket[(size_t)i * CAP + s] = p0 + u;
            else { int o = atomicAdd(&d_ovfcnt, 1); if (o < OVFCAP) d_ovflist[o] = p0 + u; }
        }
    } else if (p0 < P) {
        int i = idx[p0];
        int s = atomicAdd(&d_count[i], 1);
        if (s < CAP) d_bucket[(size_t)i * CAP + s] = p0;
        else { int o = atomicAdd(&d_ovfcnt, 1); if (o < OVFCAP) d_ovflist[o] = p0; }
    }
}

// K2: warp per pillar. SMEM staging is PAIR-PACKED: sm[pair][k] = (x_evenpt_k, x_oddpt_k).
// fma2 chain over k gives (dot_even, dot_odd) for one channel; lane does 2 channels.
__global__ void __launch_bounds__(K2_THREADS)
k2_compute(const float* __restrict__ gf, const float* __restrict__ W,
           float* __restrict__ out, int M) {
    __shared__ u64 sm[K2_WARPS][16][10];    // 16 point-pairs x 10 features, 1280B/warp

    int lane = threadIdx.x & 31;
    int wloc = threadIdx.x >> 5;
    char* smb = (char*)&sm[wloc][0][0];

    int gwarp = (blockIdx.x * K2_THREADS + threadIdx.x) >> 5;
    int nwarp = (gridDim.x * K2_THREADS) >> 5;

    float sx = d_scale[lane],      sy = d_scale[lane + 32];
    float bx = d_shift[lane],      by = d_shift[lane + 32];

    u64 wl[10], wh[10];
#pragma unroll
    for (int k = 0; k < 10; k++) {
        float a = W[k * 64 + lane] * sx;
        float b = W[k * 64 + lane + 32] * sy;
        wl[k] = pk2(a, a);
        wh[k] = pk2(b, b);
    }

    for (int i = gwarp; i < M; i += nwarp) {
        int n = d_count[i];
        if (n > CAP) n = CAP;
        float mxl = -3.402823e38f, mxh = -3.402823e38f;

        for (int base = 0; base < n; base += 32) {
            int m = n - base; if (m > 32) m = 32;
            __syncwarp();
            if (lane < m) {
                int pid = d_bucket[(size_t)i * CAP + base + lane];
                const float2* f = reinterpret_cast<const float2*>(gf + (size_t)pid * 10);
                float2 v0 = f[0], v1 = f[1], v2 = f[2], v3 = f[3], v4 = f[4];
                float vals[10] = {v0.x, v0.y, v1.x, v1.y, v2.x,
                                  v2.y, v3.x, v3.y, v4.x, v4.y};
                char* r = smb + (lane >> 1) * 80 + (lane & 1) * 4;
#pragma unroll
                for (int k = 0; k < 10; k++)
                    *reinterpret_cast<float*>(r + k * 8) = vals[k];
                // odd tail: duplicate last point into the odd slot (max-idempotent)
                if ((m & 1) && lane == m - 1) {
                    char* r2 = smb + (lane >> 1) * 80 + 4;
#pragma unroll
                    for (int k = 0; k < 10; k++)
                        *reinterpret_cast<float*>(r2 + k * 8) = vals[k];
                }
            }
            __syncwarp();

            int pairs = (m + 1) >> 1;
#pragma unroll 2
            for (int pr = 0; pr < pairs; pr++) {
                const ulonglong2* q = reinterpret_cast<const ulonglong2*>(smb + pr * 80);
                ulonglong2 q0 = q[0], q1 = q[1], q2 = q[2], q3 = q[3], q4 = q[4];
                u64 a = mul2(q0.x, wl[0]);
                u64 b = mul2(q0.x, wh[0]);
                a = fma2(q0.y, wl[1], a);  b = fma2(q0.y, wh[1], b);
                a = fma2(q1.x, wl[2], a);  b = fma2(q1.x, wh[2], b);
                a = fma2(q1.y, wl[3], a);  b = fma2(q1.y, wh[3], b);
                a = fma2(q2.x, wl[4], a);  b = fma2(q2.x, wh[4], b);
                a = fma2(q2.y, wl[5], a);  b = fma2(q2.y, wh[5], b);
                a = fma2(q3.x, wl[6], a);  b = fma2(q3.x, wh[6], b);
                a = fma2(q3.y, wl[7], a);  b = fma2(q3.y, wh[7], b);
                a = fma2(q4.x, wl[8], a);  b = fma2(q4.x, wh[8], b);
                a = fma2(q4.y, wl[9], a);  b = fma2(q4.y, wh[9], b);
                float de, dq, he, hq;
                upk2(a, de, dq);
                upk2(b, he, hq);
                mxl = fmaxf(mxl, fmaxf(de, dq));
                mxh = fmaxf(mxh, fmaxf(he, hq));
            }
        }

        float r0 = 0.0f, r1 = 0.0f;
        if (n > 0) {
            r0 = fmaxf(mxl + bx, 0.0f);
            r1 = fmaxf(mxh + by, 0.0f);
        }
        out[(size_t)i * 64 + lane]      = r0;
        out[(size_t)i * 64 + lane + 32] = r1;
    }
}

// K3: overflow cleanup (statistically never runs; kept for unconditional
// correctness). atomicMax on fp32 bits is valid: pooled values are >= 0.
__global__ void k3_overflow(const float* __restrict__ gf, const int* __restrict__ idx,
                            const float* __restrict__ W, float* __restrict__ out) {
    int nov = d_ovfcnt;
    if (nov > OVFCAP) nov = OVFCAP;
    if (nov == 0) return;

    int lane  = threadIdx.x & 31;
    int gwarp = (blockIdx.x * blockDim.x + threadIdx.x) >> 5;
    int nwarp = (gridDim.x * blockDim.x) >> 5;

    float sx = d_scale[lane], sy = d_scale[lane + 32];
    float bx = d_shift[lane], by = d_shift[lane + 32];
    float wx[10], wy[10];
#pragma unroll
    for (int k = 0; k < 10; k++) {
        wx[k] = W[k * 64 + lane] * sx;
        wy[k] = W[k * 64 + lane + 32] * sy;
    }

    for (int t = gwarp; t < nov; t += nwarp) {
        int pid = d_ovflist[t];
        int pi  = idx[pid];
        float ax = 0.0f, ay = 0.0f;
#pragma unroll
        for (int k = 0; k < 10; k++) {
            float f = gf[(size_t)pid * 10 + k];
            ax = fmaf(f, wx[k], ax);
            ay = fmaf(f, wy[k], ay);
        }
        float r0 = fmaxf(ax + bx, 0.0f);
        float r1 = fmaxf(ay + by, 0.0f);
        atomicMax((int*)&out[(size_t)pi * 64 + lane],      __float_as_int(r0));
        atomicMax((int*)&out[(size_t)pi * 64 + lane + 32], __float_as_int(r1));
    }
}

extern "C" void kernel_launch(void* const* d_in, const int* in_sizes, int n_in,
                              void* d_out, int out_size) {
    const float* gf    = (const float*)d_in[0];
    const int*   idx   = (const int*)  d_in[1];
    const float* W     = (const float*)d_in[3];
    const float* gamma = (const float*)d_in[4];
    const float* beta  = (const float*)d_in[5];
    const float* mean  = (const float*)d_in[6];
    const float* var   = (const float*)d_in[7];
    float*       out   = (float*)d_out;

    int P = in_sizes[1];
    int M = out_size / 64;

    int t  = 256;
    int g0 = ((M > 64 ? M : 64) + t - 1) / t;
    int g1 = (P / 2 + t) / t;

    k0_init<<<g0, t>>>(gamma, beta, mean, var, M);
    k1_scatter<<<g1, t>>>(idx, P);
    k2_compute<<<592, K2_THREADS>>>(gf, W, out, M);
    k3_overflow<<<2, 256>>>(gf, idx, W, out);
}